// round 14
// baseline (speedup 1.0000x reference)
#include <cuda_runtime.h>
#include <cuda_bf16.h>
#include <cuda_fp16.h>
#include <cstdint>

#define B_ 8
#define C_ 128
#define N_ 4096
#define TS 136                     // bf16 128-col tile row stride (272B)
#define YPL (64 * TS * 2)          // 17408 B: 64x128 bf16 plane
#define XPL (128 * TS * 2)         // 34816 B: 128x128 bf16 plane
#define XB64 (2 * YPL)             // 34816 B: one 64-row hi+lo X buffer
#define TSZ 72                     // z fp16 tile row stride (144B)
#define EPLZ (128 * TSZ * 2)       // 18432 B: 128x64 fp16 plane
#define ZB (2 * EPLZ)              // 36864 B per z chunk buffer (E, Xs)
#define EBLK (16 * 512 * 64)       // elems of gE per (b,nc): 128 x 4096

// ---------------- scratch (static device globals; no allocation) ----------------
__device__ __nv_bfloat16 gXhi [B_ * N_ * C_];   // theta(ref) hi, [b][n][c]
__device__ __nv_bfloat16 gXlo [B_ * N_ * C_];
__device__ __nv_bfloat16 gYhi [B_ * N_ * C_];   // phi(cur) hi, [b][m][c]
__device__ __nv_bfloat16 gYlo [B_ * N_ * C_];
__device__ __nv_bfloat16 gXthi[B_ * C_ * N_];   // theta(ref)^T hi, [b][c][n]
__device__ __nv_bfloat16 gXtlo[B_ * C_ * N_];
__device__ __half        gXs  [B_ * C_ * N_];   // invD-scaled X^T fp16, [b][c][m]
__device__ float gMhat[B_ * N_];                // per-column approx max of S[:,m]
__device__ float gSum [B_ * N_];                // sum_n exp(S-Mhat) (atomic partials)
__device__ float gZ[B_ * N_ * C_];              // attention out [b][n][c]
// exp(S - Mhat) fp16, 8x8-block layout: (b*32+nc)*EBLK + (br*512+bc)*64 + r8*8 + c8
__device__ __half gE[(size_t)B_ * N_ * N_];

// ---------------- fast exp on the FMA pipe ----------------
__device__ __forceinline__ float fexp(float x) {
    x = fmaxf(x, -87.0f);
    float t = fmaf(x, 1.4426950408889634f, 12582912.0f);
    float k = t - 12582912.0f;
    float f = fmaf(x, 1.4426950408889634f, -k);
    float p = 1.3333558146e-3f;
    p = fmaf(p, f, 9.6181291076e-3f);
    p = fmaf(p, f, 5.5504108664e-2f);
    p = fmaf(p, f, 2.4022650696e-1f);
    p = fmaf(p, f, 6.9314718056e-1f);
    p = fmaf(p, f, 1.0f);
    int ki = __float_as_int(t) - 0x4B400000;
    float sc = __int_as_float((ki + 127) << 23);
    return p * sc;
}
__device__ __forceinline__ void fma4(float4 &a, float s, const float4 &v) {
    a.x = fmaf(s, v.x, a.x); a.y = fmaf(s, v.y, a.y);
    a.z = fmaf(s, v.z, a.z); a.w = fmaf(s, v.w, a.w);
}
__device__ __forceinline__ uint32_t smem_u32(const void* p) {
    uint32_t a;
    asm("{ .reg .u64 t; cvta.to.shared.u64 t, %1; cvt.u32.u64 %0, t; }" : "=r"(a) : "l"(p));
    return a;
}
__device__ __forceinline__ uint32_t h2pack(float a, float b) {
    __half2 h = __floats2half2_rn(a, b);
    return *(uint32_t*)&h;
}

// ---------------- HMMA + ldmatrix + cp.async (base ISA) ----------------
#define LDM_X4(R0, R1, R2, R3, ADDR) \
    asm volatile("ldmatrix.sync.aligned.m8n8.x4.shared.b16 {%0,%1,%2,%3}, [%4];" \
        : "=r"(R0), "=r"(R1), "=r"(R2), "=r"(R3) : "r"(ADDR))
#define LDM_X2(R0, R1, ADDR) \
    asm volatile("ldmatrix.sync.aligned.m8n8.x2.shared.b16 {%0,%1}, [%2];" \
        : "=r"(R0), "=r"(R1) : "r"(ADDR))
#define MMA(D, A, B0, B1) \
    asm volatile("mma.sync.aligned.m16n8k16.row.col.f32.bf16.bf16.f32 " \
        "{%0,%1,%2,%3}, {%4,%5,%6,%7}, {%8,%9}, {%0,%1,%2,%3};" \
        : "+f"((D)[0]), "+f"((D)[1]), "+f"((D)[2]), "+f"((D)[3]) \
        : "r"((A)[0]), "r"((A)[1]), "r"((A)[2]), "r"((A)[3]), "r"(B0), "r"(B1))
#define MMAH(D, A, B0, B1) \
    asm volatile("mma.sync.aligned.m16n8k16.row.col.f32.f16.f16.f32 " \
        "{%0,%1,%2,%3}, {%4,%5,%6,%7}, {%8,%9}, {%0,%1,%2,%3};" \
        : "+f"((D)[0]), "+f"((D)[1]), "+f"((D)[2]), "+f"((D)[3]) \
        : "r"((A)[0]), "r"((A)[1]), "r"((A)[2]), "r"((A)[3]), "r"(B0), "r"(B1))
#define CP16(dst, src) \
    asm volatile("cp.async.cg.shared.global [%0], [%1], 16;" :: "r"(dst), "l"(src))
#define CP_COMMIT() asm volatile("cp.async.commit_group;" ::: "memory")
#define CP_WAIT0()  asm volatile("cp.async.wait_group 0;" ::: "memory")

// ---------------- proj: 1x1 conv -> split bf16 hi/lo arrays ----------------
__global__ __launch_bounds__(256) void proj_kernel(
        const float* __restrict__ in, const float* __restrict__ w,
        const float* __restrict__ bias, int which)
{
    __shared__ float it[C_ * 36];
    int b = blockIdx.y, n0 = blockIdx.x * 32;
    int tid = threadIdx.x;
    for (int i = tid; i < C_ * 32; i += 256) {
        int ci = i >> 5, nl = i & 31;
        it[ci * 36 + nl] = in[(b * C_ + ci) * N_ + n0 + nl];
    }
    __syncthreads();
    int co = tid >> 1, nlh = (tid & 1) * 16;
    float bv = bias[co];
    float4 acc[4];
#pragma unroll
    for (int q = 0; q < 4; q++) acc[q] = make_float4(bv, bv, bv, bv);
#pragma unroll 4
    for (int ci = 0; ci < C_; ci++) {
        float wv = __ldg(w + co * C_ + ci);
        const float4* zr = (const float4*)(it + ci * 36 + nlh);
#pragma unroll
        for (int q = 0; q < 4; q++) fma4(acc[q], wv, zr[q]);
    }
    float av[16];
#pragma unroll
    for (int q = 0; q < 4; q++) {
        av[4 * q] = acc[q].x; av[4 * q + 1] = acc[q].y;
        av[4 * q + 2] = acc[q].z; av[4 * q + 3] = acc[q].w;
    }
    __nv_bfloat16 h[16], l[16];
#pragma unroll
    for (int i = 0; i < 16; i++) {
        h[i] = __float2bfloat16(av[i]);
        l[i] = __float2bfloat16(av[i] - __bfloat162float(h[i]));
    }
    if (which) {
#pragma unroll
        for (int i = 0; i < 16; i++) {
            size_t idx = (size_t)(b * N_ + n0 + nlh + i) * C_ + co;
            gYhi[idx] = h[i]; gYlo[idx] = l[i];
        }
    } else {
#pragma unroll
        for (int i = 0; i < 16; i++) {
            size_t idx = (size_t)(b * N_ + n0 + nlh + i) * C_ + co;
            gXhi[idx] = h[i]; gXlo[idx] = l[i];
        }
        uint32_t ph[8], pl[8];
#pragma unroll
        for (int j = 0; j < 8; j++) {
            ph[j] = (uint32_t)__bfloat16_as_ushort(h[2 * j]) |
                    ((uint32_t)__bfloat16_as_ushort(h[2 * j + 1]) << 16);
            pl[j] = (uint32_t)__bfloat16_as_ushort(l[2 * j]) |
                    ((uint32_t)__bfloat16_as_ushort(l[2 * j + 1]) << 16);
        }
        size_t tidx = (size_t)(b * C_ + co) * N_ + n0 + nlh;
        *(uint4*)(gXthi + tidx)     = make_uint4(ph[0], ph[1], ph[2], ph[3]);
        *(uint4*)(gXthi + tidx + 8) = make_uint4(ph[4], ph[5], ph[6], ph[7]);
        *(uint4*)(gXtlo + tidx)     = make_uint4(pl[0], pl[1], pl[2], pl[3]);
        *(uint4*)(gXtlo + tidx + 8) = make_uint4(pl[4], pl[5], pl[6], pl[7]);
    }
}

// ---------------------------------------------------------------------------
// maxpass: approx column max of S (1-pass bf16 hi). CTA owns 128 m; loops 64
// n-chunks of 64 rows (double-buffered). Warp grid 2(n) x 4(m), tile 32x32.
// Also zeroes gSum for stats' atomics.
// ---------------------------------------------------------------------------
__global__ __launch_bounds__(256, 2) void maxpass_kernel()
{
    extern __shared__ char sm[];
    const int OX = XPL;                        // two 64-row hi buffers
    float* red = (float*)(sm + OX + 2 * YPL);  // [2][128]

    int tid = threadIdx.x, wid = tid >> 5, lane = tid & 31;
    int gid = lane >> 2, tig = lane & 3;
    int wn = wid >> 2, wm = wid & 3;
    int b = blockIdx.y, m0 = blockIdx.x * 128;
    uint32_t smb = smem_u32(sm);

    for (int i = tid; i < 2048; i += 256) {
        int row = i >> 4, seg = i & 15;
        CP16(smb + (uint32_t)(row * TS * 2 + seg * 16),
             gYhi + (size_t)(b * N_ + m0 + row) * C_ + seg * 8);
    }
    for (int i = tid; i < 1024; i += 256) {
        int row = i >> 4, seg = i & 15;
        CP16(smb + (uint32_t)(OX + row * TS * 2 + seg * 16),
             gXhi + (size_t)(b * N_ + row) * C_ + seg * 8);
    }
    CP_COMMIT();

    uint32_t aOff = (uint32_t)(((wn * 32 + (lane & 15)) * TS + ((lane >> 4) << 3)) * 2);
    uint32_t bHi  = smb + (uint32_t)(((wm * 32 + (lane & 7)) * TS +
                                      (((lane >> 3) & 1) << 3)) * 2);

    float mx[4][2];
#pragma unroll
    for (int nt = 0; nt < 4; nt++) { mx[nt][0] = -3.0e38f; mx[nt][1] = -3.0e38f; }

    for (int nc = 0; nc < 64; nc++) {
        CP_WAIT0();
        __syncthreads();
        if (nc + 1 < 64) {
            uint32_t nb = OX + YPL * ((nc + 1) & 1);
            for (int i = tid; i < 1024; i += 256) {
                int row = i >> 4, seg = i & 15;
                CP16(smb + nb + (uint32_t)(row * TS * 2 + seg * 16),
                     gXhi + (size_t)(b * N_ + (nc + 1) * 64 + row) * C_ + seg * 8);
            }
            CP_COMMIT();
        }

        uint32_t aHi = smb + OX + YPL * (nc & 1) + aOff;
        float sf[2][4][4];
#pragma unroll
        for (int mt = 0; mt < 2; mt++)
#pragma unroll
            for (int nt = 0; nt < 4; nt++)
#pragma unroll
                for (int q = 0; q < 4; q++) sf[mt][nt][q] = 0.0f;

#pragma unroll
        for (int k = 0; k < 8; k++) {
            uint32_t bh[4][2];
#pragma unroll
            for (int nt = 0; nt < 4; nt++)
                LDM_X2(bh[nt][0], bh[nt][1], bHi + nt * (8 * TS * 2) + k * 32);
#pragma unroll
            for (int mt = 0; mt < 2; mt++) {
                uint32_t ah[4];
                LDM_X4(ah[0], ah[1], ah[2], ah[3], aHi + mt * (16 * TS * 2) + k * 32);
#pragma unroll
                for (int nt = 0; nt < 4; nt++)
                    MMA(sf[mt][nt], ah, bh[nt][0], bh[nt][1]);
            }
        }

#pragma unroll
        for (int nt = 0; nt < 4; nt++)
#pragma unroll
            for (int j = 0; j < 2; j++)
                mx[nt][j] = fmaxf(mx[nt][j],
                    fmaxf(fmaxf(sf[0][nt][j], sf[0][nt][2 + j]),
                          fmaxf(sf[1][nt][j], sf[1][nt][2 + j])));
    }

#pragma unroll
    for (int nt = 0; nt < 4; nt++)
#pragma unroll
        for (int j = 0; j < 2; j++) {
            float v = mx[nt][j];
#pragma unroll
            for (int o = 4; o < 32; o <<= 1)
                v = fmaxf(v, __shfl_xor_sync(0xFFFFFFFFu, v, o));
            if (gid == 0)
                red[wn * 128 + wm * 32 + nt * 8 + 2 * tig + j] = v;
        }
    __syncthreads();
    if (tid < 128) {
        gMhat[b * N_ + m0 + tid] = fmaxf(red[tid], red[128 + tid]) + 0.15f;
        gSum[b * N_ + m0 + tid]  = 0.0f;
    }
}

// ---------------------------------------------------------------------------
// stats: CTA owns 128 m x 16 n-chunks (4-way n-split). Y hi+lo resident;
// 64-row X chunks double-buffered. Warp grid 2(n) x 4(m), 32x32 tiles.
// DEFERRED EPILOGUE: two accumulator slots; chunk c's MMA issues before the
// exp/store epilogue of chunk c-1 so FFMA/STG hide under HMMA.
// ---------------------------------------------------------------------------
__global__ __launch_bounds__(256) void stats_kernel()
{
    extern __shared__ char sm[];
    const int OX = 2 * XPL;                    // Y hi|lo occupy [0, 2*XPL)
    float* red = (float*)(sm + OX + 2 * XB64); // [2][128]

    int tid = threadIdx.x, wid = tid >> 5, lane = tid & 31;
    int gid = lane >> 2, tig = lane & 3;
    int wn = wid >> 2, wm = wid & 3;
    int b = blockIdx.z, mblk = blockIdx.x, m0 = mblk * 128;
    int ncBase = blockIdx.y * 16;
    uint32_t smb = smem_u32(sm);

    // prologue: Y 128 rows hi+lo + X chunk ncBase (64 rows hi+lo)
    for (int i = tid; i < 2048; i += 256) {
        int row = i >> 4, seg = i & 15;
        uint32_t doff = (uint32_t)(row * TS * 2 + seg * 16);
        CP16(smb + doff,       gYhi + (size_t)(b * N_ + m0 + row) * C_ + seg * 8);
        CP16(smb + XPL + doff, gYlo + (size_t)(b * N_ + m0 + row) * C_ + seg * 8);
    }
    for (int i = tid; i < 1024; i += 256) {
        int row = i >> 4, seg = i & 15;
        uint32_t doff = (uint32_t)(OX + row * TS * 2 + seg * 16);
        CP16(smb + doff,       gXhi + (size_t)(b * N_ + ncBase * 64 + row) * C_ + seg * 8);
        CP16(smb + doff + YPL, gXlo + (size_t)(b * N_ + ncBase * 64 + row) * C_ + seg * 8);
    }
    CP_COMMIT();

    float mh[4][2];
#pragma unroll
    for (int nt = 0; nt < 4; nt++)
#pragma unroll
        for (int j = 0; j < 2; j++)
            mh[nt][j] = gMhat[b * N_ + m0 + wm * 32 + nt * 8 + 2 * tig + j];

    uint32_t aOff = (uint32_t)(((wn * 32 + (lane & 15)) * TS + ((lane >> 4) << 3)) * 2);
    uint32_t bHi  = smb + (uint32_t)(((wm * 32 + (lane & 7)) * TS +
                                      (((lane >> 3) & 1) << 3)) * 2);
    uint32_t bLo  = bHi + XPL;

    float csum[4][2];
#pragma unroll
    for (int nt = 0; nt < 4; nt++) { csum[nt][0] = 0.f; csum[nt][1] = 0.f; }

    float sf[2][2][4][4];   // [slot][mt][nt][q]

    // deferred epilogue of chunk nc using accumulator slot S
    auto epi = [&](float (&S)[2][4][4], int nc) {
        size_t ebase = (size_t)(b * 32 + (nc >> 1)) * EBLK;
#pragma unroll
        for (int mt = 0; mt < 2; mt++) {
            int br0 = (nc & 1) * 8 + wn * 4 + mt * 2;
#pragma unroll
            for (int nt = 0; nt < 4; nt++) {
                float e0 = fminf(fexp(S[mt][nt][0] - mh[nt][0]), 60000.f);
                float e1 = fminf(fexp(S[mt][nt][1] - mh[nt][1]), 60000.f);
                float e2 = fminf(fexp(S[mt][nt][2] - mh[nt][0]), 60000.f);
                float e3 = fminf(fexp(S[mt][nt][3] - mh[nt][1]), 60000.f);
                uint32_t u01 = h2pack(e0, e1), u23 = h2pack(e2, e3);
                __half2 h01 = *(__half2*)&u01, h23 = *(__half2*)&u23;
                float2 f01 = __half22float2(h01), f23 = __half22float2(h23);
                int bc = mblk * 16 + wm * 4 + nt;
                size_t o0 = ebase + ((size_t)br0 * 512 + bc) * 64 + gid * 8 + 2 * tig;
                __stcs((uint32_t*)(gE + o0), u01);
                __stcs((uint32_t*)(gE + o0 + 32768), u23);   // br0+1 block
                csum[nt][0] += f01.x + f23.x;
                csum[nt][1] += f01.y + f23.y;
            }
        }
    };

    for (int c = 0; c < 16; c++) {
        int nc = ncBase + c;
        CP_WAIT0();
        __syncthreads();
        if (c + 1 < 16) {
            uint32_t nb = OX + XB64 * ((c + 1) & 1);
            for (int i = tid; i < 1024; i += 256) {
                int row = i >> 4, seg = i & 15;
                uint32_t doff = nb + (uint32_t)(row * TS * 2 + seg * 16);
                CP16(smb + doff,       gXhi + (size_t)(b * N_ + (nc + 1) * 64 + row) * C_ + seg * 8);
                CP16(smb + doff + YPL, gXlo + (size_t)(b * N_ + (nc + 1) * 64 + row) * C_ + seg * 8);
            }
            CP_COMMIT();
        }

        int slot = c & 1;
        uint32_t aHi = smb + OX + XB64 * slot + aOff;
        uint32_t aLo = aHi + YPL;
#pragma unroll
        for (int mt = 0; mt < 2; mt++)
#pragma unroll
            for (int nt = 0; nt < 4; nt++)
#pragma unroll
                for (int q = 0; q < 4; q++) sf[slot][mt][nt][q] = 0.0f;

#pragma unroll
        for (int k = 0; k < 8; k++) {
            uint32_t bh[4][2], bl[4][2];
#pragma unroll
            for (int nt = 0; nt < 4; nt++) {
                LDM_X2(bh[nt][0], bh[nt][1], bHi + nt * (8 * TS * 2) + k * 32);
                LDM_X2(bl[nt][0], bl[nt][1], bLo + nt * (8 * TS * 2) + k * 32);
            }
#pragma unroll
            for (int mt = 0; mt < 2; mt++) {
                uint32_t ah[4], al[4];
                LDM_X4(ah[0], ah[1], ah[2], ah[3], aHi + mt * (16 * TS * 2) + k * 32);
                LDM_X4(al[0], al[1], al[2], al[3], aLo + mt * (16 * TS * 2) + k * 32);
#pragma unroll
                for (int nt = 0; nt < 4; nt++) {
                    MMA(sf[slot][mt][nt], ah, bh[nt][0], bh[nt][1]);
                    MMA(sf[slot][mt][nt], ah, bl[nt][0], bl[nt][1]);
                    MMA(sf[slot][mt][nt], al, bh[nt][0], bh[nt][1]);
                }
            }
        }

        // epilogue of PREVIOUS chunk — overlaps with the HMMAs just issued
        if (c > 0) epi(sf[slot ^ 1], nc - 1);
    }
    epi(sf[1], ncBase + 15);   // final chunk's epilogue

    // reduce within CTA, then atomic partial into gSum
#pragma unroll
    for (int nt = 0; nt < 4; nt++)
#pragma unroll
        for (int j = 0; j < 2; j++) {
            float v = csum[nt][j];
#pragma unroll
            for (int o = 4; o < 32; o <<= 1)
                v += __shfl_xor_sync(0xFFFFFFFFu, v, o);
            if (gid == 0)
                red[wn * 128 + wm * 32 + nt * 8 + 2 * tig + j] = v;
        }
    __syncthreads();
    if (tid < 128)
        atomicAdd(&gSum[b * N_ + m0 + tid], red[tid] + red[128 + tid]);
}

// ---------------- xscale: Xs[c][m] = fp16((Xt_hi+Xt_lo)[c][m] / gSum[m]) ----
__global__ __launch_bounds__(256) void xscale_kernel()
{
    __shared__ float dv[128];
    int b = blockIdx.y, m0 = blockIdx.x * 128;
    int tid = threadIdx.x;
    if (tid < 128) dv[tid] = 1.0f / gSum[b * N_ + m0 + tid];
    __syncthreads();
    for (int i = tid; i < 128 * 64; i += 256) {
        int c = i >> 6, mp = (i & 63) * 2;
        size_t idx = (size_t)(b * C_ + c) * N_ + m0 + mp;
        uint32_t hw = *(const uint32_t*)(gXthi + idx);
        uint32_t lw = *(const uint32_t*)(gXtlo + idx);
        float v0 = __bfloat162float(__ushort_as_bfloat16((unsigned short)(hw & 0xFFFF))) +
                   __bfloat162float(__ushort_as_bfloat16((unsigned short)(lw & 0xFFFF)));
        float v1 = __bfloat162float(__ushort_as_bfloat16((unsigned short)(hw >> 16))) +
                   __bfloat162float(__ushort_as_bfloat16((unsigned short)(lw >> 16)));
        *(uint32_t*)(gXs + idx) = h2pack(v0 * dv[mp], v1 * dv[mp + 1]);
    }
}

// ---------------------------------------------------------------------------
// z: SINGLE-pass fp16 copy-fed GEMM. z[n][c] = sum_m E[n][m] * Xs[c][m].
// 128n x 128c CTA tile, 64 chunks of K=64, depth-2 ring, 2 CTAs/SM.
// ---------------------------------------------------------------------------
__global__ __launch_bounds__(256, 2) void z_kernel()
{
    extern __shared__ char sm[];
    int tid = threadIdx.x, wid = tid >> 5, lane = tid & 31;
    int gid = lane >> 2, tig = lane & 3;
    int wn = wid >> 2, wm = wid & 3;
    int b = blockIdx.y, nc = blockIdx.x, n0 = nc * 128;
    uint32_t smb = smem_u32(sm);

    size_t ebase = (size_t)(b * 32 + nc) * EBLK;
    const __half* Xsb = gXs + (size_t)b * C_ * N_;

#define Z_COPY(DST, MC) do { \
    for (int i = tid; i < 1024; i += 256) { \
        int r8 = i & 7, bcL = (i >> 3) & 7, br = i >> 6; \
        size_t src = ebase + ((size_t)br * 512 + (MC) * 8 + bcL) * 64 + r8 * 8; \
        CP16((DST) + (uint32_t)((br * 8 + r8) * (TSZ * 2) + bcL * 16), gE + src); \
    } \
    for (int i = tid; i < 1024; i += 256) { \
        int seg = i & 7, cr = i >> 3; \
        CP16((DST) + (uint32_t)(EPLZ + cr * (TSZ * 2) + seg * 16), \
             Xsb + (size_t)cr * N_ + (MC) * 64 + seg * 8); \
    } \
} while (0)

    Z_COPY(smb, 0);
    CP_COMMIT();

    uint32_t aOff = (uint32_t)(((wn * 64 + (lane & 15)) * TSZ +
                                ((lane >> 4) << 3)) * 2);
    uint32_t bOff = (uint32_t)(EPLZ + ((wm * 32 + (lane & 7)) * TSZ +
                                       (((lane >> 3) & 1) << 3)) * 2);

    float zf[4][4][4];
#pragma unroll
    for (int mt = 0; mt < 4; mt++)
#pragma unroll
        for (int nt = 0; nt < 4; nt++)
#pragma unroll
            for (int q = 0; q < 4; q++) zf[mt][nt][q] = 0.0f;

    for (int mc = 0; mc < 64; mc++) {
        CP_WAIT0();
        __syncthreads();
        if (mc + 1 < 64) {
            Z_COPY(smb + ((mc + 1) & 1) * ZB, mc + 1);
            CP_COMMIT();
        }

        uint32_t base = smb + (mc & 1) * ZB;
        uint32_t aHi = base + aOff;
        uint32_t bHi = base + bOff;
#pragma unroll
        for (int k = 0; k < 4; k++) {
            uint32_t bh[4][2];
#pragma unroll
            for (int nt = 0; nt < 4; nt++)
                LDM_X2(bh[nt][0], bh[nt][1], bHi + nt * (8 * TSZ * 2) + k * 32);
#pragma unroll
            for (int mt = 0; mt < 4; mt++) {
                uint32_t ah[4];
                LDM_X4(ah[0], ah[1], ah[2], ah[3], aHi + mt * (16 * TSZ * 2) + k * 32);
#pragma unroll
                for (int nt = 0; nt < 4; nt++)
                    MMAH(zf[mt][nt], ah, bh[nt][0], bh[nt][1]);
            }
        }
    }
#undef Z_COPY

    // epilogue -> gZ[b][n][c]
#pragma unroll
    for (int mt = 0; mt < 4; mt++) {
        int n = n0 + wn * 64 + mt * 16 + gid;
#pragma unroll
        for (int nt = 0; nt < 4; nt++) {
            int c = wm * 32 + nt * 8 + 2 * tig;
            *(float2*)(gZ + (size_t)(b * N_ + n) * C_ + c) =
                make_float2(zf[mt][nt][0], zf[mt][nt][1]);
            *(float2*)(gZ + (size_t)(b * N_ + n + 8) * C_ + c) =
                make_float2(zf[mt][nt][2], zf[mt][nt][3]);
        }
    }
}

// ---------------- outproj ----------------
__global__ __launch_bounds__(256) void outproj_kernel(
        const float* __restrict__ w, const float* __restrict__ bias,
        float* __restrict__ out)
{
    __shared__ float zt[C_ * 36];
    int b = blockIdx.y, n0 = blockIdx.x * 32;
    int tid = threadIdx.x;
    const float* Zb = gZ + (size_t)b * N_ * C_;
    for (int i = tid; i < 32 * C_; i += 256) {
        int nl = i >> 7, ci = i & 127;
        zt[ci * 36 + nl] = Zb[(n0 + nl) * C_ + ci];
    }
    __syncthreads();
    int co = tid >> 1, nlh = (tid & 1) * 16;
    float bv = bias[co];
    float4 acc[4];
#pragma unroll
    for (int q = 0; q < 4; q++) acc[q] = make_float4(bv, bv, bv, bv);
#pragma unroll 4
    for (int ci = 0; ci < C_; ci++) {
        float wv = __ldg(w + co * C_ + ci);
        const float4* zr = (const float4*)(zt + ci * 36 + nlh);
#pragma unroll
        for (int q = 0; q < 4; q++) fma4(acc[q], wv, zr[q]);
    }
    float* op = out + (b * C_ + co) * N_ + n0 + nlh;
#pragma unroll
    for (int q = 0; q < 4; q++) *(float4*)(op + 4 * q) = acc[q];
}

// ---------------------------------------------------------------------------
extern "C" void kernel_launch(void* const* d_in, const int* in_sizes, int n_in,
                              void* d_out, int out_size)
{
    const float* cur  = (const float*)d_in[0];
    const float* ref  = (const float*)d_in[1];
    const float* th_w = (const float*)d_in[2];
    const float* th_b = (const float*)d_in[3];
    const float* ph_w = (const float*)d_in[4];
    const float* ph_b = (const float*)d_in[5];
    const float* W_w  = (const float*)d_in[6];
    const float* W_b  = (const float*)d_in[7];
    float* out = (float*)d_out;

    const int max_smem   = XPL + 2 * YPL + 256 * (int)sizeof(float);      // 70656
    const int stats_smem = 2 * XPL + 2 * XB64 + 256 * (int)sizeof(float); // 140288
    const int z_smem     = 2 * ZB;                                        // 73728
    cudaFuncSetAttribute(maxpass_kernel, cudaFuncAttributeMaxDynamicSharedMemorySize, max_smem);
    cudaFuncSetAttribute(stats_kernel,   cudaFuncAttributeMaxDynamicSharedMemorySize, stats_smem);
    cudaFuncSetAttribute(z_kernel,       cudaFuncAttributeMaxDynamicSharedMemorySize, z_smem);

    dim3 blk(256);
    proj_kernel<<<dim3(N_ / 32, B_), blk>>>(ref, th_w, th_b, 0);   // X (+ X^T)
    proj_kernel<<<dim3(N_ / 32, B_), blk>>>(cur, ph_w, ph_b, 1);   // Y
    maxpass_kernel<<<dim3(N_ / 128, B_), blk, max_smem>>>();
    stats_kernel<<<dim3(N_ / 128, 4, B_), blk, stats_smem>>>();
    xscale_kernel<<<dim3(N_ / 128, B_), blk>>>();
    z_kernel<<<dim3(N_ / 128, B_), blk, z_smem>>>();
    outproj_kernel<<<dim3(N_ / 32, B_), blk>>>(W_w, W_b, out);
}

// round 15
// speedup vs baseline: 1.0432x; 1.0432x over previous
#include <cuda_runtime.h>
#include <cuda_bf16.h>
#include <cuda_fp16.h>
#include <cstdint>

#define B_ 8
#define C_ 128
#define N_ 4096
#define TS 136                     // bf16 128-col tile row stride (272B)
#define YPL (64 * TS * 2)          // 17408 B: 64x128 bf16 plane
#define XPL (128 * TS * 2)         // 34816 B: 128x128 bf16 plane
#define TSZ 72                     // z fp16 tile row stride (144B)
#define EPLZ (128 * TSZ * 2)       // 18432 B: 128x64 fp16 plane
#define ZB (2 * EPLZ)              // 36864 B per z chunk buffer (E, Xs)
#define EBLK (16 * 512 * 64)       // elems of gE per (b,nc): 128 x 4096

// ---------------- scratch (static device globals; no allocation) ----------------
__device__ __nv_bfloat16 gXhi [B_ * N_ * C_];   // theta(ref) hi, [b][n][c]
__device__ __nv_bfloat16 gXlo [B_ * N_ * C_];
__device__ __nv_bfloat16 gYhi [B_ * N_ * C_];   // phi(cur) hi, [b][m][c]
__device__ __nv_bfloat16 gYlo [B_ * N_ * C_];
__device__ __nv_bfloat16 gXthi[B_ * C_ * N_];   // theta(ref)^T hi, [b][c][n]
__device__ __nv_bfloat16 gXtlo[B_ * C_ * N_];
__device__ __half        gXs  [B_ * C_ * N_];   // invD-scaled X^T fp16, [b][c][m]
__device__ float gMhat[B_ * N_];                // per-column approx max of S[:,m]
__device__ float gSum [B_ * N_];                // sum_n exp(S-Mhat) (atomic partials)
__device__ float gZ[B_ * N_ * C_];              // attention out [b][n][c]
// exp(S - Mhat) fp16, 8x8-block layout: (b*32+nc)*EBLK + (br*512+bc)*64 + r8*8 + c8
__device__ __half gE[(size_t)B_ * N_ * N_];

// ---------------- fast exp on the FMA pipe ----------------
__device__ __forceinline__ float fexp(float x) {
    x = fmaxf(x, -87.0f);
    float t = fmaf(x, 1.4426950408889634f, 12582912.0f);
    float k = t - 12582912.0f;
    float f = fmaf(x, 1.4426950408889634f, -k);
    float p = 1.3333558146e-3f;
    p = fmaf(p, f, 9.6181291076e-3f);
    p = fmaf(p, f, 5.5504108664e-2f);
    p = fmaf(p, f, 2.4022650696e-1f);
    p = fmaf(p, f, 6.9314718056e-1f);
    p = fmaf(p, f, 1.0f);
    int ki = __float_as_int(t) - 0x4B400000;
    float sc = __int_as_float((ki + 127) << 23);
    return p * sc;
}
__device__ __forceinline__ void fma4(float4 &a, float s, const float4 &v) {
    a.x = fmaf(s, v.x, a.x); a.y = fmaf(s, v.y, a.y);
    a.z = fmaf(s, v.z, a.z); a.w = fmaf(s, v.w, a.w);
}
__device__ __forceinline__ uint32_t smem_u32(const void* p) {
    uint32_t a;
    asm("{ .reg .u64 t; cvta.to.shared.u64 t, %1; cvt.u32.u64 %0, t; }" : "=r"(a) : "l"(p));
    return a;
}
__device__ __forceinline__ uint32_t h2pack(float a, float b) {
    __half2 h = __floats2half2_rn(a, b);
    return *(uint32_t*)&h;
}

// ---------------- HMMA + ldmatrix + cp.async (base ISA) ----------------
#define LDM_X4(R0, R1, R2, R3, ADDR) \
    asm volatile("ldmatrix.sync.aligned.m8n8.x4.shared.b16 {%0,%1,%2,%3}, [%4];" \
        : "=r"(R0), "=r"(R1), "=r"(R2), "=r"(R3) : "r"(ADDR))
#define LDM_X2(R0, R1, ADDR) \
    asm volatile("ldmatrix.sync.aligned.m8n8.x2.shared.b16 {%0,%1}, [%2];" \
        : "=r"(R0), "=r"(R1) : "r"(ADDR))
#define MMA(D, A, B0, B1) \
    asm volatile("mma.sync.aligned.m16n8k16.row.col.f32.bf16.bf16.f32 " \
        "{%0,%1,%2,%3}, {%4,%5,%6,%7}, {%8,%9}, {%0,%1,%2,%3};" \
        : "+f"((D)[0]), "+f"((D)[1]), "+f"((D)[2]), "+f"((D)[3]) \
        : "r"((A)[0]), "r"((A)[1]), "r"((A)[2]), "r"((A)[3]), "r"(B0), "r"(B1))
#define MMAH(D, A, B0, B1) \
    asm volatile("mma.sync.aligned.m16n8k16.row.col.f32.f16.f16.f32 " \
        "{%0,%1,%2,%3}, {%4,%5,%6,%7}, {%8,%9}, {%0,%1,%2,%3};" \
        : "+f"((D)[0]), "+f"((D)[1]), "+f"((D)[2]), "+f"((D)[3]) \
        : "r"((A)[0]), "r"((A)[1]), "r"((A)[2]), "r"((A)[3]), "r"(B0), "r"(B1))
#define CP16(dst, src) \
    asm volatile("cp.async.cg.shared.global [%0], [%1], 16;" :: "r"(dst), "l"(src))
#define CP_COMMIT() asm volatile("cp.async.commit_group;" ::: "memory")
#define CP_WAIT0()  asm volatile("cp.async.wait_group 0;" ::: "memory")

// ---------------- proj: 1x1 conv -> split bf16 hi/lo arrays ----------------
__global__ __launch_bounds__(256) void proj_kernel(
        const float* __restrict__ in, const float* __restrict__ w,
        const float* __restrict__ bias, int which)
{
    __shared__ float it[C_ * 36];
    int b = blockIdx.y, n0 = blockIdx.x * 32;
    int tid = threadIdx.x;
    for (int i = tid; i < C_ * 32; i += 256) {
        int ci = i >> 5, nl = i & 31;
        it[ci * 36 + nl] = in[(b * C_ + ci) * N_ + n0 + nl];
    }
    __syncthreads();
    int co = tid >> 1, nlh = (tid & 1) * 16;
    float bv = bias[co];
    float4 acc[4];
#pragma unroll
    for (int q = 0; q < 4; q++) acc[q] = make_float4(bv, bv, bv, bv);
#pragma unroll 4
    for (int ci = 0; ci < C_; ci++) {
        float wv = __ldg(w + co * C_ + ci);
        const float4* zr = (const float4*)(it + ci * 36 + nlh);
#pragma unroll
        for (int q = 0; q < 4; q++) fma4(acc[q], wv, zr[q]);
    }
    float av[16];
#pragma unroll
    for (int q = 0; q < 4; q++) {
        av[4 * q] = acc[q].x; av[4 * q + 1] = acc[q].y;
        av[4 * q + 2] = acc[q].z; av[4 * q + 3] = acc[q].w;
    }
    __nv_bfloat16 h[16], l[16];
#pragma unroll
    for (int i = 0; i < 16; i++) {
        h[i] = __float2bfloat16(av[i]);
        l[i] = __float2bfloat16(av[i] - __bfloat162float(h[i]));
    }
    if (which) {
#pragma unroll
        for (int i = 0; i < 16; i++) {
            size_t idx = (size_t)(b * N_ + n0 + nlh + i) * C_ + co;
            gYhi[idx] = h[i]; gYlo[idx] = l[i];
        }
    } else {
#pragma unroll
        for (int i = 0; i < 16; i++) {
            size_t idx = (size_t)(b * N_ + n0 + nlh + i) * C_ + co;
            gXhi[idx] = h[i]; gXlo[idx] = l[i];
        }
        uint32_t ph[8], pl[8];
#pragma unroll
        for (int j = 0; j < 8; j++) {
            ph[j] = (uint32_t)__bfloat16_as_ushort(h[2 * j]) |
                    ((uint32_t)__bfloat16_as_ushort(h[2 * j + 1]) << 16);
            pl[j] = (uint32_t)__bfloat16_as_ushort(l[2 * j]) |
                    ((uint32_t)__bfloat16_as_ushort(l[2 * j + 1]) << 16);
        }
        size_t tidx = (size_t)(b * C_ + co) * N_ + n0 + nlh;
        *(uint4*)(gXthi + tidx)     = make_uint4(ph[0], ph[1], ph[2], ph[3]);
        *(uint4*)(gXthi + tidx + 8) = make_uint4(ph[4], ph[5], ph[6], ph[7]);
        *(uint4*)(gXtlo + tidx)     = make_uint4(pl[0], pl[1], pl[2], pl[3]);
        *(uint4*)(gXtlo + tidx + 8) = make_uint4(pl[4], pl[5], pl[6], pl[7]);
    }
}

// ---------------------------------------------------------------------------
// maxpass: approx column max of S (1-pass bf16 hi). CTA owns 128 m; loops 64
// n-chunks of 64 rows (double-buffered). Warp grid 2(n) x 4(m), tile 32x32.
// Also zeroes gSum for stats' atomics.
// ---------------------------------------------------------------------------
__global__ __launch_bounds__(256, 2) void maxpass_kernel()
{
    extern __shared__ char sm[];
    const int OX = XPL;                        // two 64-row hi buffers
    float* red = (float*)(sm + OX + 2 * YPL);  // [2][128]

    int tid = threadIdx.x, wid = tid >> 5, lane = tid & 31;
    int gid = lane >> 2, tig = lane & 3;
    int wn = wid >> 2, wm = wid & 3;
    int b = blockIdx.y, m0 = blockIdx.x * 128;
    uint32_t smb = smem_u32(sm);

    for (int i = tid; i < 2048; i += 256) {
        int row = i >> 4, seg = i & 15;
        CP16(smb + (uint32_t)(row * TS * 2 + seg * 16),
             gYhi + (size_t)(b * N_ + m0 + row) * C_ + seg * 8);
    }
    for (int i = tid; i < 1024; i += 256) {
        int row = i >> 4, seg = i & 15;
        CP16(smb + (uint32_t)(OX + row * TS * 2 + seg * 16),
             gXhi + (size_t)(b * N_ + row) * C_ + seg * 8);
    }
    CP_COMMIT();

    uint32_t aOff = (uint32_t)(((wn * 32 + (lane & 15)) * TS + ((lane >> 4) << 3)) * 2);
    uint32_t bHi  = smb + (uint32_t)(((wm * 32 + (lane & 7)) * TS +
                                      (((lane >> 3) & 1) << 3)) * 2);

    float mx[4][2];
#pragma unroll
    for (int nt = 0; nt < 4; nt++) { mx[nt][0] = -3.0e38f; mx[nt][1] = -3.0e38f; }

    for (int nc = 0; nc < 64; nc++) {
        CP_WAIT0();
        __syncthreads();
        if (nc + 1 < 64) {
            uint32_t nb = OX + YPL * ((nc + 1) & 1);
            for (int i = tid; i < 1024; i += 256) {
                int row = i >> 4, seg = i & 15;
                CP16(smb + nb + (uint32_t)(row * TS * 2 + seg * 16),
                     gXhi + (size_t)(b * N_ + (nc + 1) * 64 + row) * C_ + seg * 8);
            }
            CP_COMMIT();
        }

        uint32_t aHi = smb + OX + YPL * (nc & 1) + aOff;
        float sf[2][4][4];
#pragma unroll
        for (int mt = 0; mt < 2; mt++)
#pragma unroll
            for (int nt = 0; nt < 4; nt++)
#pragma unroll
                for (int q = 0; q < 4; q++) sf[mt][nt][q] = 0.0f;

#pragma unroll
        for (int k = 0; k < 8; k++) {
            uint32_t bh[4][2];
#pragma unroll
            for (int nt = 0; nt < 4; nt++)
                LDM_X2(bh[nt][0], bh[nt][1], bHi + nt * (8 * TS * 2) + k * 32);
#pragma unroll
            for (int mt = 0; mt < 2; mt++) {
                uint32_t ah[4];
                LDM_X4(ah[0], ah[1], ah[2], ah[3], aHi + mt * (16 * TS * 2) + k * 32);
#pragma unroll
                for (int nt = 0; nt < 4; nt++)
                    MMA(sf[mt][nt], ah, bh[nt][0], bh[nt][1]);
            }
        }

#pragma unroll
        for (int nt = 0; nt < 4; nt++)
#pragma unroll
            for (int j = 0; j < 2; j++)
                mx[nt][j] = fmaxf(mx[nt][j],
                    fmaxf(fmaxf(sf[0][nt][j], sf[0][nt][2 + j]),
                          fmaxf(sf[1][nt][j], sf[1][nt][2 + j])));
    }

#pragma unroll
    for (int nt = 0; nt < 4; nt++)
#pragma unroll
        for (int j = 0; j < 2; j++) {
            float v = mx[nt][j];
#pragma unroll
            for (int o = 4; o < 32; o <<= 1)
                v = fmaxf(v, __shfl_xor_sync(0xFFFFFFFFu, v, o));
            if (gid == 0)
                red[wn * 128 + wm * 32 + nt * 8 + 2 * tig + j] = v;
        }
    __syncthreads();
    if (tid < 128) {
        gMhat[b * N_ + m0 + tid] = fmaxf(red[tid], red[128 + tid]) + 0.15f;
        gSum[b * N_ + m0 + tid]  = 0.0f;
    }
}

// ---------------------------------------------------------------------------
// stats: CTA owns 64 m x 8 n-chunks of 128 rows (4-way n-split), 2 CTAs/SM.
// Y hi+lo resident (64 rows); single X buffer (128 rows hi+lo). Warp grid
// 4(n) x 2(m), 32x32 tiles. Copies serialized per chunk; the SIBLING CTA's
// MMA hides copy+epilogue phases. Register column sums -> atomicAdd.
// ---------------------------------------------------------------------------
__global__ __launch_bounds__(256, 2) void stats_kernel()
{
    extern __shared__ char sm[];
    const int OX = 2 * YPL;                    // Y hi|lo occupy [0, 2*YPL)
    float* red = (float*)(sm + OX + 2 * XPL);  // [4][64]

    int tid = threadIdx.x, wid = tid >> 5, lane = tid & 31;
    int gid = lane >> 2, tig = lane & 3;
    int wn = wid >> 1, wm = wid & 1;
    int b = blockIdx.z, mblk = blockIdx.x, m0 = mblk * 64;
    int ncBase = blockIdx.y * 8;
    uint32_t smb = smem_u32(sm);

    // Y resident: 64 rows hi+lo
    for (int i = tid; i < 1024; i += 256) {
        int row = i >> 4, seg = i & 15;
        uint32_t doff = (uint32_t)(row * TS * 2 + seg * 16);
        CP16(smb + doff,       gYhi + (size_t)(b * N_ + m0 + row) * C_ + seg * 8);
        CP16(smb + YPL + doff, gYlo + (size_t)(b * N_ + m0 + row) * C_ + seg * 8);
    }
    CP_COMMIT();

    float mh[4][2];
#pragma unroll
    for (int nt = 0; nt < 4; nt++)
#pragma unroll
        for (int j = 0; j < 2; j++)
            mh[nt][j] = gMhat[b * N_ + m0 + wm * 32 + nt * 8 + 2 * tig + j];

    uint32_t aOff = (uint32_t)(((wn * 32 + (lane & 15)) * TS + ((lane >> 4) << 3)) * 2);
    uint32_t bHi  = smb + (uint32_t)(((wm * 32 + (lane & 7)) * TS +
                                      (((lane >> 3) & 1) << 3)) * 2);
    uint32_t bLo  = bHi + YPL;

    float csum[4][2];
#pragma unroll
    for (int nt = 0; nt < 4; nt++) { csum[nt][0] = 0.f; csum[nt][1] = 0.f; }

    for (int c = 0; c < 8; c++) {
        int nc = ncBase + c;
        __syncthreads();   // all warps done reading X buffer from prev chunk
        for (int i = tid; i < 2048; i += 256) {
            int row = i >> 4, seg = i & 15;
            uint32_t doff = (uint32_t)(OX + row * TS * 2 + seg * 16);
            CP16(smb + doff,       gXhi + (size_t)(b * N_ + nc * 128 + row) * C_ + seg * 8);
            CP16(smb + doff + XPL, gXlo + (size_t)(b * N_ + nc * 128 + row) * C_ + seg * 8);
        }
        CP_COMMIT(); CP_WAIT0();
        __syncthreads();

        uint32_t aHi = smb + OX + aOff;
        uint32_t aLo = aHi + XPL;
        float sf[2][4][4];
#pragma unroll
        for (int mt = 0; mt < 2; mt++)
#pragma unroll
            for (int nt = 0; nt < 4; nt++)
#pragma unroll
                for (int q = 0; q < 4; q++) sf[mt][nt][q] = 0.0f;

#pragma unroll
        for (int k = 0; k < 8; k++) {
            uint32_t bh[4][2], bl[4][2];
#pragma unroll
            for (int nt = 0; nt < 4; nt++) {
                LDM_X2(bh[nt][0], bh[nt][1], bHi + nt * (8 * TS * 2) + k * 32);
                LDM_X2(bl[nt][0], bl[nt][1], bLo + nt * (8 * TS * 2) + k * 32);
            }
#pragma unroll
            for (int mt = 0; mt < 2; mt++) {
                uint32_t ah[4], al[4];
                LDM_X4(ah[0], ah[1], ah[2], ah[3], aHi + mt * (16 * TS * 2) + k * 32);
                LDM_X4(al[0], al[1], al[2], al[3], aLo + mt * (16 * TS * 2) + k * 32);
#pragma unroll
                for (int nt = 0; nt < 4; nt++) {
                    MMA(sf[mt][nt], ah, bh[nt][0], bh[nt][1]);
                    MMA(sf[mt][nt], ah, bl[nt][0], bl[nt][1]);
                    MMA(sf[mt][nt], al, bh[nt][0], bh[nt][1]);
                }
            }
        }

        // epilogue: exp(S - Mhat), fp16 8x8-block stores, register sums
        size_t ebase = (size_t)(b * 32 + nc) * EBLK;
#pragma unroll
        for (int mt = 0; mt < 2; mt++) {
            int br0 = wn * 4 + mt * 2;
#pragma unroll
            for (int nt = 0; nt < 4; nt++) {
                float e0 = fminf(fexp(sf[mt][nt][0] - mh[nt][0]), 60000.f);
                float e1 = fminf(fexp(sf[mt][nt][1] - mh[nt][1]), 60000.f);
                float e2 = fminf(fexp(sf[mt][nt][2] - mh[nt][0]), 60000.f);
                float e3 = fminf(fexp(sf[mt][nt][3] - mh[nt][1]), 60000.f);
                uint32_t u01 = h2pack(e0, e1), u23 = h2pack(e2, e3);
                __half2 h01 = *(__half2*)&u01, h23 = *(__half2*)&u23;
                float2 f01 = __half22float2(h01), f23 = __half22float2(h23);
                int bc = mblk * 8 + wm * 4 + nt;
                size_t o0 = ebase + ((size_t)br0 * 512 + bc) * 64 + gid * 8 + 2 * tig;
                __stcs((uint32_t*)(gE + o0), u01);
                __stcs((uint32_t*)(gE + o0 + 32768), u23);   // br0+1 block
                csum[nt][0] += f01.x + f23.x;
                csum[nt][1] += f01.y + f23.y;
            }
        }
    }

    // reduce within CTA, then atomic partial into gSum
#pragma unroll
    for (int nt = 0; nt < 4; nt++)
#pragma unroll
        for (int j = 0; j < 2; j++) {
            float v = csum[nt][j];
#pragma unroll
            for (int o = 4; o < 32; o <<= 1)
                v += __shfl_xor_sync(0xFFFFFFFFu, v, o);
            if (gid == 0)
                red[wn * 64 + wm * 32 + nt * 8 + 2 * tig + j] = v;
        }
    __syncthreads();
    if (tid < 64)
        atomicAdd(&gSum[b * N_ + m0 + tid],
                  red[tid] + red[64 + tid] + red[128 + tid] + red[192 + tid]);
}

// ---------------- xscale: Xs[c][m] = fp16((Xt_hi+Xt_lo)[c][m] / gSum[m]) ----
__global__ __launch_bounds__(256) void xscale_kernel()
{
    __shared__ float dv[128];
    int b = blockIdx.y, m0 = blockIdx.x * 128;
    int tid = threadIdx.x;
    if (tid < 128) dv[tid] = 1.0f / gSum[b * N_ + m0 + tid];
    __syncthreads();
    for (int i = tid; i < 128 * 64; i += 256) {
        int c = i >> 6, mp = (i & 63) * 2;
        size_t idx = (size_t)(b * C_ + c) * N_ + m0 + mp;
        uint32_t hw = *(const uint32_t*)(gXthi + idx);
        uint32_t lw = *(const uint32_t*)(gXtlo + idx);
        float v0 = __bfloat162float(__ushort_as_bfloat16((unsigned short)(hw & 0xFFFF))) +
                   __bfloat162float(__ushort_as_bfloat16((unsigned short)(lw & 0xFFFF)));
        float v1 = __bfloat162float(__ushort_as_bfloat16((unsigned short)(hw >> 16))) +
                   __bfloat162float(__ushort_as_bfloat16((unsigned short)(lw >> 16)));
        *(uint32_t*)(gXs + idx) = h2pack(v0 * dv[mp], v1 * dv[mp + 1]);
    }
}

// ---------------------------------------------------------------------------
// z: SINGLE-pass fp16 copy-fed GEMM. z[n][c] = sum_m E[n][m] * Xs[c][m].
// 128n x 128c CTA tile, 64 chunks of K=64, depth-2 ring, 2 CTAs/SM.
// ---------------------------------------------------------------------------
__global__ __launch_bounds__(256, 2) void z_kernel()
{
    extern __shared__ char sm[];
    int tid = threadIdx.x, wid = tid >> 5, lane = tid & 31;
    int gid = lane >> 2, tig = lane & 3;
    int wn = wid >> 2, wm = wid & 3;
    int b = blockIdx.y, nc = blockIdx.x, n0 = nc * 128;
    uint32_t smb = smem_u32(sm);

    size_t ebase = (size_t)(b * 32 + nc) * EBLK;
    const __half* Xsb = gXs + (size_t)b * C_ * N_;

#define Z_COPY(DST, MC) do { \
    for (int i = tid; i < 1024; i += 256) { \
        int r8 = i & 7, bcL = (i >> 3) & 7, br = i >> 6; \
        size_t src = ebase + ((size_t)br * 512 + (MC) * 8 + bcL) * 64 + r8 * 8; \
        CP16((DST) + (uint32_t)((br * 8 + r8) * (TSZ * 2) + bcL * 16), gE + src); \
    } \
    for (int i = tid; i < 1024; i += 256) { \
        int seg = i & 7, cr = i >> 3; \
        CP16((DST) + (uint32_t)(EPLZ + cr * (TSZ * 2) + seg * 16), \
             Xsb + (size_t)cr * N_ + (MC) * 64 + seg * 8); \
    } \
} while (0)

    Z_COPY(smb, 0);
    CP_COMMIT();

    uint32_t aOff = (uint32_t)(((wn * 64 + (lane & 15)) * TSZ +
                                ((lane >> 4) << 3)) * 2);
    uint32_t bOff = (uint32_t)(EPLZ + ((wm * 32 + (lane & 7)) * TSZ +
                                       (((lane >> 3) & 1) << 3)) * 2);

    float zf[4][4][4];
#pragma unroll
    for (int mt = 0; mt < 4; mt++)
#pragma unroll
        for (int nt = 0; nt < 4; nt++)
#pragma unroll
            for (int q = 0; q < 4; q++) zf[mt][nt][q] = 0.0f;

    for (int mc = 0; mc < 64; mc++) {
        CP_WAIT0();
        __syncthreads();
        if (mc + 1 < 64) {
            Z_COPY(smb + ((mc + 1) & 1) * ZB, mc + 1);
            CP_COMMIT();
        }

        uint32_t base = smb + (mc & 1) * ZB;
        uint32_t aHi = base + aOff;
        uint32_t bHi = base + bOff;
#pragma unroll
        for (int k = 0; k < 4; k++) {
            uint32_t bh[4][2];
#pragma unroll
            for (int nt = 0; nt < 4; nt++)
                LDM_X2(bh[nt][0], bh[nt][1], bHi + nt * (8 * TSZ * 2) + k * 32);
#pragma unroll
            for (int mt = 0; mt < 4; mt++) {
                uint32_t ah[4];
                LDM_X4(ah[0], ah[1], ah[2], ah[3], aHi + mt * (16 * TSZ * 2) + k * 32);
#pragma unroll
                for (int nt = 0; nt < 4; nt++)
                    MMAH(zf[mt][nt], ah, bh[nt][0], bh[nt][1]);
            }
        }
    }
#undef Z_COPY

    // epilogue -> gZ[b][n][c]
#pragma unroll
    for (int mt = 0; mt < 4; mt++) {
        int n = n0 + wn * 64 + mt * 16 + gid;
#pragma unroll
        for (int nt = 0; nt < 4; nt++) {
            int c = wm * 32 + nt * 8 + 2 * tig;
            *(float2*)(gZ + (size_t)(b * N_ + n) * C_ + c) =
                make_float2(zf[mt][nt][0], zf[mt][nt][1]);
            *(float2*)(gZ + (size_t)(b * N_ + n + 8) * C_ + c) =
                make_float2(zf[mt][nt][2], zf[mt][nt][3]);
        }
    }
}

// ---------------- outproj ----------------
__global__ __launch_bounds__(256) void outproj_kernel(
        const float* __restrict__ w, const float* __restrict__ bias,
        float* __restrict__ out)
{
    __shared__ float zt[C_ * 36];
    int b = blockIdx.y, n0 = blockIdx.x * 32;
    int tid = threadIdx.x;
    const float* Zb = gZ + (size_t)b * N_ * C_;
    for (int i = tid; i < 32 * C_; i += 256) {
        int nl = i >> 7, ci = i & 127;
        zt[ci * 36 + nl] = Zb[(n0 + nl) * C_ + ci];
    }
    __syncthreads();
    int co = tid >> 1, nlh = (tid & 1) * 16;
    float bv = bias[co];
    float4 acc[4];
#pragma unroll
    for (int q = 0; q < 4; q++) acc[q] = make_float4(bv, bv, bv, bv);
#pragma unroll 4
    for (int ci = 0; ci < C_; ci++) {
        float wv = __ldg(w + co * C_ + ci);
        const float4* zr = (const float4*)(zt + ci * 36 + nlh);
#pragma unroll
        for (int q = 0; q < 4; q++) fma4(acc[q], wv, zr[q]);
    }
    float* op = out + (b * C_ + co) * N_ + n0 + nlh;
#pragma unroll
    for (int q = 0; q < 4; q++) *(float4*)(op + 4 * q) = acc[q];
}

// ---------------------------------------------------------------------------
extern "C" void kernel_launch(void* const* d_in, const int* in_sizes, int n_in,
                              void* d_out, int out_size)
{
    const float* cur  = (const float*)d_in[0];
    const float* ref  = (const float*)d_in[1];
    const float* th_w = (const float*)d_in[2];
    const float* th_b = (const float*)d_in[3];
    const float* ph_w = (const float*)d_in[4];
    const float* ph_b = (const float*)d_in[5];
    const float* W_w  = (const float*)d_in[6];
    const float* W_b  = (const float*)d_in[7];
    float* out = (float*)d_out;

    const int max_smem   = XPL + 2 * YPL + 256 * (int)sizeof(float);     // 70656
    const int stats_smem = 2 * YPL + 2 * XPL + 256 * (int)sizeof(float); // 105472
    const int z_smem     = 2 * ZB;                                       // 73728
    cudaFuncSetAttribute(maxpass_kernel, cudaFuncAttributeMaxDynamicSharedMemorySize, max_smem);
    cudaFuncSetAttribute(stats_kernel,   cudaFuncAttributeMaxDynamicSharedMemorySize, stats_smem);
    cudaFuncSetAttribute(z_kernel,       cudaFuncAttributeMaxDynamicSharedMemorySize, z_smem);

    dim3 blk(256);
    proj_kernel<<<dim3(N_ / 32, B_), blk>>>(ref, th_w, th_b, 0);   // X (+ X^T)
    proj_kernel<<<dim3(N_ / 32, B_), blk>>>(cur, ph_w, ph_b, 1);   // Y
    maxpass_kernel<<<dim3(N_ / 128, B_), blk, max_smem>>>();
    stats_kernel<<<dim3(N_ / 64, 4, B_), blk, stats_smem>>>();
    xscale_kernel<<<dim3(N_ / 128, B_), blk>>>();
    z_kernel<<<dim3(N_ / 128, B_), blk, z_smem>>>();
    outproj_kernel<<<dim3(N_ / 32, B_), blk>>>(W_w, W_b, out);
}